// round 2
// baseline (speedup 1.0000x reference)
#include <cuda_runtime.h>
#include <cstdint>

#define T_STEPS 512
#define HID 32

// Scratch (allocation-free rule: __device__ globals)
// proj2[bucket][lane] = prescaled (P[l]*CI, P[32+l]*CF, P[64+l]*CC, P[96+l]*CO)
__device__ __align__(16) float g_proj2[4096 * 32 * 4];
// Rpack[j][lane]     = prescaled (R[j][l]*CI, R[j][32+l]*CF, R[j][64+l]*CC, R[j][96+l]*CO)
__device__ __align__(16) float g_Rpack[32 * 32 * 4];

// scale constants folded into weights: sigmoid(x)=rcp(1+ex2(-x*log2e)), tanh(x)=1-2*rcp(1+ex2(x*2log2e))
#define C_SIG  (-1.4426950408889634f)
#define C_TANH ( 2.8853900817779268f)

// ---------- packed f32x2 helpers ----------
__device__ __forceinline__ void fma2(unsigned long long& acc, unsigned long long a, unsigned long long b) {
    asm("fma.rn.f32x2 %0, %1, %2, %0;" : "+l"(acc) : "l"(a), "l"(b));
}
__device__ __forceinline__ void add2(unsigned long long& acc, unsigned long long a) {
    asm("add.rn.f32x2 %0, %0, %1;" : "+l"(acc) : "l"(a));
}
__device__ __forceinline__ void unpk2(unsigned long long v, float& lo, float& hi) {
    asm("mov.b64 {%0, %1}, %2;" : "=f"(lo), "=f"(hi) : "l"(v));
}

// ---------- MUFU primitives ----------
__device__ __forceinline__ float fex2(float x) { float y; asm("ex2.approx.f32 %0, %1;" : "=f"(y) : "f"(x)); return y; }
__device__ __forceinline__ float frcp(float x) { float y; asm("rcp.approx.f32 %0, %1;" : "=f"(y) : "f"(x)); return y; }
// inputs already prescaled by C_SIG / C_TANH
__device__ __forceinline__ float sig_pre(float xs)  { return frcp(1.0f + fex2(xs)); }
__device__ __forceinline__ float tanh_pre(float xs) { return 1.0f - 2.0f * frcp(1.0f + fex2(xs)); }
__device__ __forceinline__ float tanh_full(float x) { return tanh_pre(C_TANH * x); }

// ---------- merged prep: pack+prescale rec_kernel, build per-bucket projection table ----------
__global__ void prep_all(const float* __restrict__ emb, const float* __restrict__ K,
                         const float* __restrict__ R, int nbuckets) {
    int idx = blockIdx.x * blockDim.x + threadIdx.x;
    if (idx < 32 * 32) {
        int j = idx >> 5, l = idx & 31;
        float4 v = make_float4(R[j * 128 + l] * C_SIG,  R[j * 128 + 32 + l] * C_SIG,
                               R[j * 128 + 64 + l] * C_TANH, R[j * 128 + 96 + l] * C_SIG);
        *(float4*)&g_Rpack[idx * 4] = v;
    }
    int id = idx >> 5, l = idx & 31;
    if (id >= nbuckets) return;
    float a = 0.f, b = 0.f, c = 0.f, d = 0.f;
#pragma unroll
    for (int e = 0; e < 16; e++) {
        float xv = emb[id * 16 + e];
        const float* kr = K + e * 128 + l;
        a = fmaf(xv, kr[0],  a);
        b = fmaf(xv, kr[32], b);
        c = fmaf(xv, kr[64], c);
        d = fmaf(xv, kr[96], d);
    }
    *(float4*)&g_proj2[idx * 4] = make_float4(a * C_SIG, b * C_SIG, c * C_TANH, d * C_SIG);
}

// ---------- main: warp-per-batch LSTM scan + fused head ----------
__global__ __launch_bounds__(128, 3) void lstm_main(
    const int* __restrict__ ids,
    const float* __restrict__ w1, const float* __restrict__ b1,
    const float* __restrict__ w2, const float* __restrict__ b2,
    float* __restrict__ out, int B)
{
    __shared__ __align__(16) float hb[4][2][64];   // per-warp double-buffered (h,h) pairs
    const int w = threadIdx.x >> 5;
    const int lane = threadIdx.x & 31;
    const int b = blockIdx.x * 4 + w;
    if (b >= B) return;   // uniform per warp; no block-level syncs in this kernel

    // recurrent weights: 32 j-rows x 4 owned columns as 2 f32x2 pairs, loaded pre-paired
    unsigned long long RA[32], RB[32];
    const ulonglong2* Rp = (const ulonglong2*)g_Rpack;
#pragma unroll
    for (int j = 0; j < 32; j++) {
        ulonglong2 r = Rp[j * 32 + lane];
        RA[j] = r.x;
        RB[j] = r.y;
    }

    const ulonglong2* Pp = (const ulonglong2*)g_proj2;
    const int* idrow = ids + b * T_STEPS;
    int idreg = idrow[lane];                              // ids for steps 0..31
    int id0 = __shfl_sync(0xffffffffu, idreg, 0);
    ulonglong2 p = Pp[id0 * 32 + lane];                   // proj for step 0 (prescaled)

    *(float2*)&hb[w][0][2 * lane] = make_float2(0.f, 0.f);  // h_0 = 0
    __syncwarp();

    float c = 0.f;
    for (int t = 0; t < T_STEPS; t++) {
        // prefetch proj for step t+1 (hidden behind this step's math)
        int tn = t + 1;
        if (((tn & 31) == 0) && (tn < T_STEPS)) idreg = idrow[tn + lane];
        int idn = __shfl_sync(0xffffffffu, idreg, tn & 31);
        ulonglong2 pn = Pp[idn * 32 + lane];

        // 4 independent accumulator chains (depth 16 each)
        unsigned long long accA0 = p.x;   // (zi', zf')
        unsigned long long accB0 = p.y;   // (zc', zo')
        unsigned long long accA1 = 0ull;
        unsigned long long accB1 = 0ull;

        const ulonglong2* hp = (const ulonglong2*)&hb[w][t & 1][0];
#pragma unroll
        for (int k = 0; k < 16; k++) {
            ulonglong2 hv = hp[k];          // ((h2k,h2k),(h2k+1,h2k+1)) broadcast LDS.128
            fma2(accA0, RA[2 * k],     hv.x);
            fma2(accB0, RB[2 * k],     hv.x);
            fma2(accA1, RA[2 * k + 1], hv.y);
            fma2(accB1, RB[2 * k + 1], hv.y);
        }
        add2(accA0, accA1);
        add2(accB0, accB1);

        float zi, zf, zc, zo;
        unpk2(accA0, zi, zf);
        unpk2(accB0, zc, zo);
        float ig = sig_pre(zi);
        float fg = sig_pre(zf);
        float og = sig_pre(zo);
        float gg = tanh_pre(zc);
        c = fmaf(fg, c, ig * gg);
        float h = og * tanh_full(c);

        *(float2*)&hb[w][tn & 1][2 * lane] = make_float2(h, h);
        __syncwarp();
        p = pn;
    }

    // head: y = relu(h @ w1 + b1) @ w2 + b2  (h lives in hb[w][0], duplicated pairs)
    float s = b1[lane];
#pragma unroll
    for (int l = 0; l < HID; l++)
        s = fmaf(hb[w][0][2 * l], w1[l * 32 + lane], s);
    float r = fmaxf(s, 0.f) * w2[lane];
#pragma unroll
    for (int off = 16; off; off >>= 1)
        r += __shfl_xor_sync(0xffffffffu, r, off);
    if (lane == 0) out[b] = r + b2[0];
}

extern "C" void kernel_launch(void* const* d_in, const int* in_sizes, int n_in,
                              void* d_out, int out_size)
{
    const int*   ids  = (const int*)d_in[0];
    const float* emb  = (const float*)d_in[1];
    const float* kern = (const float*)d_in[2];
    const float* rec  = (const float*)d_in[3];
    const float* w1   = (const float*)d_in[4];
    const float* b1   = (const float*)d_in[5];
    const float* w2   = (const float*)d_in[6];
    const float* b2   = (const float*)d_in[7];

    int B = in_sizes[0] / T_STEPS;
    int nbuckets = in_sizes[1] / 16;
    if (nbuckets > 4096) nbuckets = 4096;

    int prep_threads = nbuckets * 32;
    if (prep_threads < 1024) prep_threads = 1024;
    prep_all<<<(prep_threads + 127) / 128, 128>>>(emb, kern, rec, nbuckets);
    lstm_main<<<(B + 3) / 4, 128>>>(ids, w1, b1, w2, b2, (float*)d_out, B);
}

// round 3
// speedup vs baseline: 1.3797x; 1.3797x over previous
#include <cuda_runtime.h>
#include <cstdint>

#define T_STEPS 512

// Scratch (allocation-free rule: __device__ globals)
// proj[bucket][lane] = (Pi*0.5, Pf*0.5, Pc*1.0, Po*0.5)  (0.5 = sigmoid-via-tanh prescale)
__device__ __align__(16) float g_proj2[4096 * 32 * 4];
// Rpack: ull at ((c*16 + j)*32 + lane) = (R[2j][col]*s_c, R[2j+1][col]*s_c), col = c*32+lane
__device__ __align__(16) unsigned long long g_R[4 * 16 * 32];

// ---------- packed f32x2 helpers ----------
__device__ __forceinline__ void fma2(unsigned long long& acc, unsigned long long a, unsigned long long b) {
    asm("fma.rn.f32x2 %0, %1, %2, %0;" : "+l"(acc) : "l"(a), "l"(b));
}
__device__ __forceinline__ void unpk2(unsigned long long v, float& lo, float& hi) {
    asm("mov.b64 {%0, %1}, %2;" : "=f"(lo), "=f"(hi) : "l"(v));
}
// ---------- MUFU tanh (sm_75+) ----------
__device__ __forceinline__ float ftanh(float x) {
    float y; asm("tanh.approx.f32 %0, %1;" : "=f"(y) : "f"(x)); return y;
}

// ---------- merged prep ----------
__global__ void prep_all(const float* __restrict__ emb, const float* __restrict__ K,
                         const float* __restrict__ R, int nbuckets) {
    int idx = blockIdx.x * blockDim.x + threadIdx.x;
    // pack rec_kernel: 2048 entries (c, j, lane)
    if (idx < 4 * 16 * 32) {
        int lane = idx & 31, j = (idx >> 5) & 15, c = idx >> 9;
        int col = c * 32 + lane;
        float s = (c == 2) ? 1.0f : 0.5f;
        float lo = R[(2 * j) * 128 + col] * s;
        float hi = R[(2 * j + 1) * 128 + col] * s;
        unsigned long long v;
        asm("mov.b64 %0, {%1, %2};" : "=l"(v) : "f"(lo), "f"(hi));
        g_R[idx] = v;
    }
    // per-bucket projection table
    int id = idx >> 5, l = idx & 31;
    if (id >= nbuckets) return;
    float a = 0.f, b = 0.f, c = 0.f, d = 0.f;
#pragma unroll
    for (int e = 0; e < 16; e++) {
        float xv = emb[id * 16 + e];
        const float* kr = K + e * 128 + l;
        a = fmaf(xv, kr[0],  a);
        b = fmaf(xv, kr[32], b);
        c = fmaf(xv, kr[64], c);
        d = fmaf(xv, kr[96], d);
    }
    *(float4*)&g_proj2[idx * 4] = make_float4(a * 0.5f, b * 0.5f, c, d * 0.5f);
}

// ---------- main: warp-per-batch LSTM scan + fused head ----------
__global__ __launch_bounds__(128, 3) void lstm_main(
    const int* __restrict__ ids,
    const float* __restrict__ w1, const float* __restrict__ b1,
    const float* __restrict__ w2, const float* __restrict__ b2,
    float* __restrict__ out, int B)
{
    __shared__ __align__(16) float hb[4][2][32];   // per-warp double-buffered h (plain)
    const int w = threadIdx.x >> 5;
    const int lane = threadIdx.x & 31;
    const int b = blockIdx.x * 4 + w;
    if (b >= B) return;   // uniform per warp

    // weights: per lane, 4 owned cols x 16 j-pairs (prescaled)
    unsigned long long RW[4][16];
#pragma unroll
    for (int c = 0; c < 4; c++)
#pragma unroll
        for (int j = 0; j < 16; j++)
            RW[c][j] = g_R[(c * 16 + j) * 32 + lane];

    const float4* Pp = (const float4*)g_proj2;
    const int* idrow = ids + b * T_STEPS;
    int idreg = idrow[lane];                              // ids for steps 0..31
    int id0 = __shfl_sync(0xffffffffu, idreg, 0);
    float4 p = Pp[id0 * 32 + lane];                       // proj for step 0 (prescaled)

    hb[w][0][lane] = 0.f;                                 // h_0 = 0
    __syncwarp();

    float cst = 0.f;
    for (int t = 0; t < T_STEPS; t++) {
        // prefetch proj for step t+1 (hidden behind this step's math)
        int tn = t + 1;
        if (((tn & 31) == 0) && (tn < T_STEPS)) idreg = idrow[tn + lane];
        int idn = __shfl_sync(0xffffffffu, idreg, tn & 31);
        float4 pn = Pp[idn * 32 + lane];

        unsigned long long a0 = 0ull, a1 = 0ull, a2 = 0ull, a3 = 0ull;
        const ulonglong2* hp = (const ulonglong2*)&hb[w][t & 1][0];
#pragma unroll
        for (int k = 0; k < 8; k++) {
            ulonglong2 hv = hp[k];              // (h4k,h4k+1),(h4k+2,h4k+3) broadcast LDS.128
            fma2(a0, RW[0][2 * k], hv.x);
            fma2(a1, RW[1][2 * k], hv.x);
            fma2(a2, RW[2][2 * k], hv.x);
            fma2(a3, RW[3][2 * k], hv.x);
            fma2(a0, RW[0][2 * k + 1], hv.y);
            fma2(a1, RW[1][2 * k + 1], hv.y);
            fma2(a2, RW[2][2 * k + 1], hv.y);
            fma2(a3, RW[3][2 * k + 1], hv.y);
        }
        float e0, o0, e1, o1, e2, o2, e3, o3;
        unpk2(a0, e0, o0);
        unpk2(a1, e1, o1);
        unpk2(a2, e2, o2);
        unpk2(a3, e3, o3);
        float zi = p.x + e0 + o0;
        float zf = p.y + e1 + o1;
        float zc = p.z + e2 + o2;
        float zo = p.w + e3 + o3;

        float ig = fmaf(ftanh(zi), 0.5f, 0.5f);   // sigmoid via tanh (input prescaled x0.5)
        float fg = fmaf(ftanh(zf), 0.5f, 0.5f);
        float og = fmaf(ftanh(zo), 0.5f, 0.5f);
        float gg = ftanh(zc);
        cst = fmaf(fg, cst, ig * gg);
        float h = og * ftanh(cst);

        hb[w][tn & 1][lane] = h;
        __syncwarp();
        p = pn;
    }

    // head: y = relu(h @ w1 + b1) @ w2 + b2  (h lives in hb[w][0])
    float s = b1[lane];
#pragma unroll
    for (int l = 0; l < 32; l++)
        s = fmaf(hb[w][0][l], w1[l * 32 + lane], s);
    float r = fmaxf(s, 0.f) * w2[lane];
#pragma unroll
    for (int off = 16; off; off >>= 1)
        r += __shfl_xor_sync(0xffffffffu, r, off);
    if (lane == 0) out[b] = r + b2[0];
}

extern "C" void kernel_launch(void* const* d_in, const int* in_sizes, int n_in,
                              void* d_out, int out_size)
{
    const int*   ids  = (const int*)d_in[0];
    const float* emb  = (const float*)d_in[1];
    const float* kern = (const float*)d_in[2];
    const float* rec  = (const float*)d_in[3];
    const float* w1   = (const float*)d_in[4];
    const float* b1   = (const float*)d_in[5];
    const float* w2   = (const float*)d_in[6];
    const float* b2   = (const float*)d_in[7];

    int B = in_sizes[0] / T_STEPS;
    int nbuckets = in_sizes[1] / 16;
    if (nbuckets > 4096) nbuckets = 4096;

    int prep_threads = nbuckets * 32;
    if (prep_threads < 2048) prep_threads = 2048;
    prep_all<<<(prep_threads + 127) / 128, 128>>>(emb, kern, rec, nbuckets);
    lstm_main<<<(B + 3) / 4, 128>>>(ids, w1, b1, w2, b2, (float*)d_out, B);
}